// round 16
// baseline (speedup 1.0000x reference)
#include <cuda_runtime.h>
#include <math.h>
#include <stdint.h>

#define BATCH 2
#define CH    64
#define CK    8
#define NPIX  9216   // 96*96
#define NB    256    // depth bins
#define BPB   16     // bins per binkv block
#define DLO   (-4.0f)
#define DSCALE ((float)NB / 8.0f)
#define LOG2E 1.4426950408889634f

// Scratch (allocation-free rule: __device__ globals). No cross-replay state.
__device__ float g_l2c[BATCH * NB];          // log2(count) or -1e5
__device__ float g_k[BATCH * NB * CK];       // tf32, pre-scaled by log2(e)
__device__ float g_v[BATCH * CH * NB];       // TRANSPOSED [b][c][bin], tf32-rounded

__device__ __forceinline__ float to_tf32(float x) {
    float r; asm("cvt.rna.tf32.f32 %0, %1;" : "=f"(r) : "f"(x)); return r;
}
__device__ __forceinline__ float ex2f(float x) {
    float r; asm("ex2.approx.f32 %0, %1;" : "=f"(r) : "f"(x)); return r;
}
__device__ __forceinline__ void mma4(float* d, const float* a, float b0, float b1) {
    asm("mma.sync.aligned.m16n8k8.row.col.f32.tf32.tf32.f32 "
        "{%0,%1,%2,%3},{%4,%5,%6,%7},{%8,%9},{%0,%1,%2,%3};"
        : "+f"(d[0]), "+f"(d[1]), "+f"(d[2]), "+f"(d[3])
        : "r"(__float_as_uint(a[0])), "r"(__float_as_uint(a[1])),
          "r"(__float_as_uint(a[2])), "r"(__float_as_uint(a[3])),
          "r"(__float_as_uint(b0)), "r"(__float_as_uint(b1)));
}

// Shared smem budget for both kernels
#define RPAD  68
#define RSZ   (128 * RPAD)
#define REDB  1408
#define SMEM_FLOATS (REDB + 4 * RSZ)   // 36224 floats = 144896 B

// ---------------------------------------------------------------------------
// Kernel 1: fused histogram + per-bin k/v projection (R15 structure; single
// tf32 k output, tighter depth range).
// ---------------------------------------------------------------------------
#define BCNT  0        // 256 ints
#define BSUM  256      // 256 floats
#define BWA   512      // 64
#define BBA   576      // 64
#define BBD   640      // 64
#define BBC   704      // 8
#define BWC   712      // 8 x 65
#define BWD   1232     // 64 x 65

__global__ void __launch_bounds__(512) binkv_kernel(
        const float* __restrict__ depth,
        const float* __restrict__ wa, const float* __restrict__ ba,
        const float* __restrict__ wc, const float* __restrict__ bc,
        const float* __restrict__ wd, const float* __restrict__ bd) {
    extern __shared__ float sb[];
    int* scnt = (int*)&sb[BCNT];

    const int t = threadIdx.x;
    const int w = t >> 5;
    const int b = blockIdx.y;
    const int bin0 = blockIdx.x * BPB;

    if (t < 256) { scnt[t] = 0; sb[BSUM + t] = 0.0f; }
    if (t < CH) { sb[BWA + t] = wa[t]; sb[BBA + t] = ba[t]; sb[BBD + t] = bd[t]; }
    if (t < CK) sb[BBC + t] = bc[t];
    if (t < CK * CH) sb[BWC + (t >> 6) * 65 + (t & 63)] = wc[t];
#pragma unroll
    for (int i = 0; i < 8; i++) {
        const int idx = t + i * 512;
        sb[BWD + (idx >> 6) * 65 + (idx & 63)] = wd[idx];
    }
    __syncthreads();

    const float* dep = depth + (size_t)b * NPIX;
#pragma unroll
    for (int i = 0; i < NPIX / 512; i++) {
        const float v = dep[t + i * 512];
        int bi = (int)((v - DLO) * DSCALE);
        bi = min(max(bi, 0), NB - 1);
        const int local = bi - bin0;
        if ((unsigned)local < BPB) {
            atomicAdd(&scnt[w * BPB + local], 1);
            atomicAdd(&sb[BSUM + w * BPB + local], v);
        }
    }
    __syncthreads();

    const int bin = t & (BPB - 1);
    const int g   = t >> 4;           // 0..31
    int   cnt = 0;
    float s   = 0.0f;
#pragma unroll
    for (int ww = 0; ww < 16; ww++) { cnt += scnt[ww * BPB + bin]; s += sb[BSUM + ww * BPB + bin]; }
    const float d = (cnt > 0) ? (s / (float)cnt) : 0.0f;
    if (t < BPB) g_l2c[b * NB + bin0 + t] = (cnt > 0) ? log2f((float)cnt) : -100000.0f;

    float acck = (g < 8) ? sb[BBC + g] : 0.0f;
    float a0 = sb[BBD + 2 * g], a1 = sb[BBD + 2 * g + 1];
#pragma unroll 8
    for (int c = 0; c < CH; c++) {
        const float df = fmaxf(fmaf(sb[BWA + c], d, sb[BBA + c]), 0.0f);  // broadcast
        if (g < 8) acck = fmaf(sb[BWC + g * 65 + c], df, acck);
        a0 = fmaf(sb[BWD + (2 * g) * 65 + c], df, a0);
        a1 = fmaf(sb[BWD + (2 * g + 1) * 65 + c], df, a1);
    }
    if (g < 8)
        g_k[((size_t)b * NB + bin0 + bin) * CK + g] = to_tf32(acck * LOG2E);
    float* vo = g_v + (size_t)b * CH * NB + bin0 + bin;
    vo[(size_t)(2 * g) * NB]     = to_tf32(a0);
    vo[(size_t)(2 * g + 1) * NB] = to_tf32(a1);
}

// ---------------------------------------------------------------------------
// Kernel 2: fused qproj + binned attention. Phase A: SINGLE tf32 MMA per
// score chunk (compensation dropped; accuracy budget reclaimed via tighter
// bin range). Mainloop sync-free; epilogue unchanged.
// ---------------------------------------------------------------------------
#define KPAD  12
#define VPAD  264
#define SL    0
#define SQ    128
#define SL2C  1152
#define SKH   1408          // 256 x 12 (single k)
#define SV    4480          // 64 x 264
#define SWB   21376
#define SBB   21888
#define FMT   21896         // 64 x 128 (prologue only)

__global__ void __launch_bounds__(512, 1) attn_kernel(const float* __restrict__ fm,
                                                      const float* __restrict__ wb,
                                                      const float* __restrict__ bb,
                                                      float* __restrict__ out) {
    extern __shared__ float sm[];

    const int t    = threadIdx.x;
    const int lane = t & 31;
    const int gid  = lane >> 2;
    const int tig  = lane & 3;
    const int wid  = t >> 5;
    const int qi   = wid & 3;
    const int kh   = wid >> 2;
    const int b    = blockIdx.y;
    const int n0   = blockIdx.x * 128;

    // ---- prologue ----
    if (t < 128) sm[SL + t] = 0.0f;
    sm[SWB + t] = wb[t];
    if (t < 8)  sm[SBB + t] = bb[t];
    if (t < NB) sm[SL2C + t] = g_l2c[b * NB + t];

    {   // K: 2048 floats = 512 float4, 1 per thread
        const float4 k4 = ((const float4*)(g_k + (size_t)b * NB * CK))[t];
        const int off = (t >> 1) * KPAD + (t & 1) * 4;
        *(float4*)&sm[SKH + off] = k4;
    }
    {
        const float4* vg4 = (const float4*)(g_v + (size_t)b * CH * NB);
#pragma unroll
        for (int j = 0; j < 8; j++) {
            const int i  = t + j * 512;
            const int c  = i >> 6;
            const int b4 = (i & 63) * 4;
            *(float4*)&sm[SV + c * VPAD + b4] = vg4[i];
        }
    }
    {
        const float* fmb = fm + (size_t)b * CH * NPIX + n0;
#pragma unroll
        for (int i = 0; i < 4; i++) {
            const int idx = t + i * 512;
            const int c   = idx >> 5;
            const int r4  = (idx & 31) * 4;
            *(float4*)&sm[FMT + c * 128 + r4] = *(const float4*)&fmb[(size_t)c * NPIX + r4];
        }
    }
    __syncthreads();

    {
        const int r  = t & 127;
        const int jp = t >> 7;
        float a0 = sm[SBB + 2 * jp], a1 = sm[SBB + 2 * jp + 1];
#pragma unroll 8
        for (int c = 0; c < CH; c++) {
            const float fv = sm[FMT + c * 128 + r];
            a0 = fmaf(sm[SWB + (2 * jp) * CH + c], fv, a0);
            a1 = fmaf(sm[SWB + (2 * jp + 1) * CH + c], fv, a1);
        }
        sm[SQ + r * 8 + 2 * jp]     = a0;
        sm[SQ + r * 8 + 2 * jp + 1] = a1;
    }
    __syncthreads();

    // ---- Q A-fragments (single tf32) ----
    float qf[2][4];
#pragma unroll
    for (int sub = 0; sub < 2; sub++) {
        const int qbase = qi * 32 + sub * 16;
        qf[sub][0] = to_tf32(sm[SQ + (qbase + gid) * 8 + tig]);
        qf[sub][1] = to_tf32(sm[SQ + (qbase + gid + 8) * 8 + tig]);
        qf[sub][2] = to_tf32(sm[SQ + (qbase + gid) * 8 + tig + 4]);
        qf[sub][3] = to_tf32(sm[SQ + (qbase + gid + 8) * 8 + tig + 4]);
    }

    float acc[2][8][4] = {};
    float lpart[2][2]  = {};

    // ---- mainloop: sync-free, 1 score MMA + 16 PV MMAs per chunk ----
#pragma unroll
    for (int mt = 0; mt < NB / 64; mt++) {
#pragma unroll
        for (int mc = 0; mc < 2; mc++) {
            const int row = mt * 64 + kh * 16 + mc * 8;
            const float* kr = &sm[SKH + (row + gid) * KPAD];
            const float b0 = kr[tig], b1 = kr[tig + 4];
            const float2 lc = *(const float2*)&sm[SL2C + row + 2 * tig];

            float p[2][4];
#pragma unroll
            for (int sub = 0; sub < 2; sub++) {
                float d[4] = {lc.x, lc.y, lc.x, lc.y};
                mma4(d, qf[sub], b0, b1);
                p[sub][0] = to_tf32(ex2f(d[0]));
                p[sub][1] = to_tf32(ex2f(d[1]));
                p[sub][2] = to_tf32(ex2f(d[2]));
                p[sub][3] = to_tf32(ex2f(d[3]));
                lpart[sub][0] += p[sub][0] + p[sub][1];
                lpart[sub][1] += p[sub][2] + p[sub][3];
            }
            const float a0[4] = {p[0][0], p[0][2], p[0][1], p[0][3]};
            const float a1[4] = {p[1][0], p[1][2], p[1][1], p[1][3]};
#pragma unroll
            for (int nc = 0; nc < 8; nc++) {
                const float2 bv = *(const float2*)&sm[SV + (nc * 8 + gid) * VPAD + row + 2 * tig];
                mma4(acc[0][nc], a0, bv.x, bv.y);
                mma4(acc[1][nc], a1, bv.x, bv.y);
            }
        }
    }

    // ---- row-sum reduction ----
#pragma unroll
    for (int sub = 0; sub < 2; sub++)
#pragma unroll
        for (int h = 0; h < 2; h++) {
            float v = lpart[sub][h];
            v += __shfl_xor_sync(0xffffffff, v, 1);
            v += __shfl_xor_sync(0xffffffff, v, 2);
            if (tig == 0) atomicAdd(&sm[SL + qi * 32 + sub * 16 + gid + h * 8], v);
        }
    __syncthreads();

    // ---- one-round partial dump ----
    {
        float* reg = sm + REDB + kh * RSZ;
#pragma unroll
        for (int sub = 0; sub < 2; sub++) {
            const int qrow = qi * 32 + sub * 16 + gid;
#pragma unroll
            for (int nc = 0; nc < 8; nc++) {
                const int c = nc * 8 + 2 * tig;
                *(float2*)&reg[qrow * RPAD + c]       = make_float2(acc[sub][nc][0], acc[sub][nc][1]);
                *(float2*)&reg[(qrow + 8) * RPAD + c] = make_float2(acc[sub][nc][2], acc[sub][nc][3]);
            }
        }
    }
    __syncthreads();

    // ---- sum 4 partials, scale, coalesced store ----
    {
        const int q  = t & 127;
        const int cq = t >> 7;
        const float rl = 1.0f / sm[SL + q];
        const int base = q * RPAD + cq * 16;
        float* ob = out + ((size_t)b * CH + cq * 16) * NPIX + n0 + q;
#pragma unroll
        for (int j = 0; j < 4; j++) {
            float4 s0 = *(float4*)&sm[REDB + 0 * RSZ + base + j * 4];
            float4 s1 = *(float4*)&sm[REDB + 1 * RSZ + base + j * 4];
            float4 s2 = *(float4*)&sm[REDB + 2 * RSZ + base + j * 4];
            float4 s3 = *(float4*)&sm[REDB + 3 * RSZ + base + j * 4];
            ob[(size_t)(j * 4 + 0) * NPIX] = (s0.x + s1.x + s2.x + s3.x) * rl;
            ob[(size_t)(j * 4 + 1) * NPIX] = (s0.y + s1.y + s2.y + s3.y) * rl;
            ob[(size_t)(j * 4 + 2) * NPIX] = (s0.z + s1.z + s2.z + s3.z) * rl;
            ob[(size_t)(j * 4 + 3) * NPIX] = (s0.w + s1.w + s2.w + s3.w) * rl;
        }
    }
}

// ---------------------------------------------------------------------------
extern "C" void kernel_launch(void* const* d_in, const int* in_sizes, int n_in,
                              void* d_out, int out_size) {
    const float* fm    = (const float*)d_in[0];
    const float* depth = (const float*)d_in[1];
    const float* wa    = (const float*)d_in[2];
    const float* ba    = (const float*)d_in[3];
    const float* wb    = (const float*)d_in[4];
    const float* bb    = (const float*)d_in[5];
    const float* wc    = (const float*)d_in[6];
    const float* bc    = (const float*)d_in[7];
    const float* wd    = (const float*)d_in[8];
    const float* bd    = (const float*)d_in[9];
    float* out = (float*)d_out;

    const int smem_bytes = SMEM_FLOATS * sizeof(float);
    cudaFuncSetAttribute(attn_kernel,  cudaFuncAttributeMaxDynamicSharedMemorySize, smem_bytes);
    cudaFuncSetAttribute(binkv_kernel, cudaFuncAttributeMaxDynamicSharedMemorySize, smem_bytes);

    binkv_kernel<<<dim3(NB / BPB, BATCH), 512, smem_bytes>>>(depth, wa, ba, wc, bc, wd, bd);
    attn_kernel<<<dim3(NPIX / 128, BATCH), 512, smem_bytes>>>(fm, wb, bb, out);
}

// round 17
// speedup vs baseline: 1.0122x; 1.0122x over previous
#include <cuda_runtime.h>
#include <math.h>
#include <stdint.h>

#define BATCH 2
#define CH    64
#define CK    8
#define NPIX  9216   // 96*96
#define NB    256    // depth bins
#define BPB   16     // bins per binkv block
#define DLO   (-4.0f)
#define DSCALE ((float)NB / 8.0f)
#define LOG2E 1.4426950408889634f

// Scratch (allocation-free rule: __device__ globals). No cross-replay state.
__device__ float g_l2c[BATCH * NB];          // log2(count) or -1e5
__device__ float g_k[BATCH * NB * CK];       // tf32, pre-scaled by log2(e)
__device__ float g_v[BATCH * CH * NB];       // TRANSPOSED [b][c][bin], tf32-rounded

__device__ __forceinline__ float to_tf32(float x) {
    float r; asm("cvt.rna.tf32.f32 %0, %1;" : "=f"(r) : "f"(x)); return r;
}
__device__ __forceinline__ float ex2f(float x) {
    float r; asm("ex2.approx.f32 %0, %1;" : "=f"(r) : "f"(x)); return r;
}
__device__ __forceinline__ void mma4(float* d, const float* a, float b0, float b1) {
    asm("mma.sync.aligned.m16n8k8.row.col.f32.tf32.tf32.f32 "
        "{%0,%1,%2,%3},{%4,%5,%6,%7},{%8,%9},{%0,%1,%2,%3};"
        : "+f"(d[0]), "+f"(d[1]), "+f"(d[2]), "+f"(d[3])
        : "r"(__float_as_uint(a[0])), "r"(__float_as_uint(a[1])),
          "r"(__float_as_uint(a[2])), "r"(__float_as_uint(a[3])),
          "r"(__float_as_uint(b0)), "r"(__float_as_uint(b1)));
}

// attn smem budget
#define RPAD  68
#define RSZ   (128 * RPAD)
#define REDB  1408
#define SMEM_FLOATS (REDB + 4 * RSZ)   // 36224 floats = 144896 B

// ---------------------------------------------------------------------------
// Kernel 1: fused histogram + per-bin k/v projection (R16 logic, SMALL STATIC
// smem so its blocks can co-reside with PDL-overlapped attn CTAs).
// grid = (NB/BPB, BATCH), block = 512.
// ---------------------------------------------------------------------------
__global__ void __launch_bounds__(512) binkv_kernel(
        const float* __restrict__ depth,
        const float* __restrict__ wa, const float* __restrict__ ba,
        const float* __restrict__ wc, const float* __restrict__ bc,
        const float* __restrict__ wd, const float* __restrict__ bd) {
    __shared__ int   scnt[256];
    __shared__ float ssum[256];
    __shared__ float s_wa[CH], s_ba[CH], s_bd[CH], s_bc[CK];
    __shared__ float s_wc[CK * 65];
    __shared__ float s_wd[CH * 65];

    const int t = threadIdx.x;
    const int w = t >> 5;
    const int b = blockIdx.y;
    const int bin0 = blockIdx.x * BPB;

    if (t < 256) { scnt[t] = 0; ssum[t] = 0.0f; }
    if (t < CH) { s_wa[t] = wa[t]; s_ba[t] = ba[t]; s_bd[t] = bd[t]; }
    if (t < CK) s_bc[t] = bc[t];
    if (t < CK * CH) s_wc[(t >> 6) * 65 + (t & 63)] = wc[t];
#pragma unroll
    for (int i = 0; i < 8; i++) {
        const int idx = t + i * 512;
        s_wd[(idx >> 6) * 65 + (idx & 63)] = wd[idx];
    }
    __syncthreads();

    const float* dep = depth + (size_t)b * NPIX;
#pragma unroll
    for (int i = 0; i < NPIX / 512; i++) {
        const float v = dep[t + i * 512];
        int bi = (int)((v - DLO) * DSCALE);
        bi = min(max(bi, 0), NB - 1);
        const int local = bi - bin0;
        if ((unsigned)local < BPB) {
            atomicAdd(&scnt[w * BPB + local], 1);
            atomicAdd(&ssum[w * BPB + local], v);
        }
    }
    __syncthreads();

    const int bin = t & (BPB - 1);
    const int g   = t >> 4;           // 0..31
    int   cnt = 0;
    float s   = 0.0f;
#pragma unroll
    for (int ww = 0; ww < 16; ww++) { cnt += scnt[ww * BPB + bin]; s += ssum[ww * BPB + bin]; }
    const float d = (cnt > 0) ? (s / (float)cnt) : 0.0f;
    if (t < BPB) g_l2c[b * NB + bin0 + t] = (cnt > 0) ? log2f((float)cnt) : -100000.0f;

    float acck = (g < 8) ? s_bc[g] : 0.0f;
    float a0 = s_bd[2 * g], a1 = s_bd[2 * g + 1];
#pragma unroll 8
    for (int c = 0; c < CH; c++) {
        const float df = fmaxf(fmaf(s_wa[c], d, s_ba[c]), 0.0f);  // broadcast
        if (g < 8) acck = fmaf(s_wc[g * 65 + c], df, acck);
        a0 = fmaf(s_wd[(2 * g) * 65 + c], df, a0);
        a1 = fmaf(s_wd[(2 * g + 1) * 65 + c], df, a1);
    }
    if (g < 8)
        g_k[((size_t)b * NB + bin0 + bin) * CK + g] = to_tf32(acck * LOG2E);
    float* vo = g_v + (size_t)b * CH * NB + bin0 + bin;
    vo[(size_t)(2 * g) * NB]     = to_tf32(a0);
    vo[(size_t)(2 * g + 1) * NB] = to_tf32(a1);
}

// ---------------------------------------------------------------------------
// Kernel 2: fused qproj + binned attention, PDL-overlapped.
//   Part 1 (runs CONCURRENTLY with binkv): fm tile load + qproj.
//   cudaGridDependencySynchronize() gates Part 2 (K/V/l2c consumption).
// ---------------------------------------------------------------------------
#define KPAD  12
#define VPAD  264
#define SL    0
#define SQ    128
#define SL2C  1152
#define SKH   1408          // 256 x 12
#define SV    4480          // 64 x 264
#define SWB   21376
#define SBB   21888
#define FMT   21896         // 64 x 128 (prologue only)

__global__ void __launch_bounds__(512, 1) attn_kernel(const float* __restrict__ fm,
                                                      const float* __restrict__ wb,
                                                      const float* __restrict__ bb,
                                                      float* __restrict__ out) {
    extern __shared__ float sm[];

    const int t    = threadIdx.x;
    const int lane = t & 31;
    const int gid  = lane >> 2;
    const int tig  = lane & 3;
    const int wid  = t >> 5;
    const int qi   = wid & 3;
    const int kh   = wid >> 2;
    const int b    = blockIdx.y;
    const int n0   = blockIdx.x * 128;

    // ---- Part 1: independent of binkv output ----
    if (t < 128) sm[SL + t] = 0.0f;
    sm[SWB + t] = wb[t];
    if (t < 8)  sm[SBB + t] = bb[t];
    {
        const float* fmb = fm + (size_t)b * CH * NPIX + n0;
#pragma unroll
        for (int i = 0; i < 4; i++) {
            const int idx = t + i * 512;
            const int c   = idx >> 5;
            const int r4  = (idx & 31) * 4;
            *(float4*)&sm[FMT + c * 128 + r4] = *(const float4*)&fmb[(size_t)c * NPIX + r4];
        }
    }
    __syncthreads();
    {
        const int r  = t & 127;
        const int jp = t >> 7;
        float a0 = sm[SBB + 2 * jp], a1 = sm[SBB + 2 * jp + 1];
#pragma unroll 8
        for (int c = 0; c < CH; c++) {
            const float fv = sm[FMT + c * 128 + r];
            a0 = fmaf(sm[SWB + (2 * jp) * CH + c], fv, a0);
            a1 = fmaf(sm[SWB + (2 * jp + 1) * CH + c], fv, a1);
        }
        sm[SQ + r * 8 + 2 * jp]     = a0;
        sm[SQ + r * 8 + 2 * jp + 1] = a1;
    }

    // ---- wait for binkv (PDL) ----
    cudaGridDependencySynchronize();

    // ---- Part 2: consume K/V/l2c ----
    if (t < NB) sm[SL2C + t] = g_l2c[b * NB + t];
    {
        const float4 k4 = ((const float4*)(g_k + (size_t)b * NB * CK))[t];
        const int off = (t >> 1) * KPAD + (t & 1) * 4;
        *(float4*)&sm[SKH + off] = k4;
    }
    {
        const float4* vg4 = (const float4*)(g_v + (size_t)b * CH * NB);
#pragma unroll
        for (int j = 0; j < 8; j++) {
            const int i  = t + j * 512;
            const int c  = i >> 6;
            const int b4 = (i & 63) * 4;
            *(float4*)&sm[SV + c * VPAD + b4] = vg4[i];
        }
    }
    __syncthreads();   // K/V/SQ all visible

    float qf[2][4];
#pragma unroll
    for (int sub = 0; sub < 2; sub++) {
        const int qbase = qi * 32 + sub * 16;
        qf[sub][0] = to_tf32(sm[SQ + (qbase + gid) * 8 + tig]);
        qf[sub][1] = to_tf32(sm[SQ + (qbase + gid + 8) * 8 + tig]);
        qf[sub][2] = to_tf32(sm[SQ + (qbase + gid) * 8 + tig + 4]);
        qf[sub][3] = to_tf32(sm[SQ + (qbase + gid + 8) * 8 + tig + 4]);
    }

    float acc[2][8][4] = {};
    float lpart[2][2]  = {};

    // ---- mainloop: sync-free ----
#pragma unroll
    for (int mt = 0; mt < NB / 64; mt++) {
#pragma unroll
        for (int mc = 0; mc < 2; mc++) {
            const int row = mt * 64 + kh * 16 + mc * 8;
            const float* kr = &sm[SKH + (row + gid) * KPAD];
            const float b0 = kr[tig], b1 = kr[tig + 4];
            const float2 lc = *(const float2*)&sm[SL2C + row + 2 * tig];

            float p[2][4];
#pragma unroll
            for (int sub = 0; sub < 2; sub++) {
                float d[4] = {lc.x, lc.y, lc.x, lc.y};
                mma4(d, qf[sub], b0, b1);
                p[sub][0] = to_tf32(ex2f(d[0]));
                p[sub][1] = to_tf32(ex2f(d[1]));
                p[sub][2] = to_tf32(ex2f(d[2]));
                p[sub][3] = to_tf32(ex2f(d[3]));
                lpart[sub][0] += p[sub][0] + p[sub][1];
                lpart[sub][1] += p[sub][2] + p[sub][3];
            }
            const float a0[4] = {p[0][0], p[0][2], p[0][1], p[0][3]};
            const float a1[4] = {p[1][0], p[1][2], p[1][1], p[1][3]};
#pragma unroll
            for (int nc = 0; nc < 8; nc++) {
                const float2 bv = *(const float2*)&sm[SV + (nc * 8 + gid) * VPAD + row + 2 * tig];
                mma4(acc[0][nc], a0, bv.x, bv.y);
                mma4(acc[1][nc], a1, bv.x, bv.y);
            }
        }
    }

    // ---- row-sum reduction ----
#pragma unroll
    for (int sub = 0; sub < 2; sub++)
#pragma unroll
        for (int h = 0; h < 2; h++) {
            float v = lpart[sub][h];
            v += __shfl_xor_sync(0xffffffff, v, 1);
            v += __shfl_xor_sync(0xffffffff, v, 2);
            if (tig == 0) atomicAdd(&sm[SL + qi * 32 + sub * 16 + gid + h * 8], v);
        }
    __syncthreads();

    // ---- one-round partial dump ----
    {
        float* reg = sm + REDB + kh * RSZ;
#pragma unroll
        for (int sub = 0; sub < 2; sub++) {
            const int qrow = qi * 32 + sub * 16 + gid;
#pragma unroll
            for (int nc = 0; nc < 8; nc++) {
                const int c = nc * 8 + 2 * tig;
                *(float2*)&reg[qrow * RPAD + c]       = make_float2(acc[sub][nc][0], acc[sub][nc][1]);
                *(float2*)&reg[(qrow + 8) * RPAD + c] = make_float2(acc[sub][nc][2], acc[sub][nc][3]);
            }
        }
    }
    __syncthreads();

    // ---- sum 4 partials, scale, coalesced store ----
    {
        const int q  = t & 127;
        const int cq = t >> 7;
        const float rl = 1.0f / sm[SL + q];
        const int base = q * RPAD + cq * 16;
        float* ob = out + ((size_t)b * CH + cq * 16) * NPIX + n0 + q;
#pragma unroll
        for (int j = 0; j < 4; j++) {
            float4 s0 = *(float4*)&sm[REDB + 0 * RSZ + base + j * 4];
            float4 s1 = *(float4*)&sm[REDB + 1 * RSZ + base + j * 4];
            float4 s2 = *(float4*)&sm[REDB + 2 * RSZ + base + j * 4];
            float4 s3 = *(float4*)&sm[REDB + 3 * RSZ + base + j * 4];
            ob[(size_t)(j * 4 + 0) * NPIX] = (s0.x + s1.x + s2.x + s3.x) * rl;
            ob[(size_t)(j * 4 + 1) * NPIX] = (s0.y + s1.y + s2.y + s3.y) * rl;
            ob[(size_t)(j * 4 + 2) * NPIX] = (s0.z + s1.z + s2.z + s3.z) * rl;
            ob[(size_t)(j * 4 + 3) * NPIX] = (s0.w + s1.w + s2.w + s3.w) * rl;
        }
    }
}

// ---------------------------------------------------------------------------
extern "C" void kernel_launch(void* const* d_in, const int* in_sizes, int n_in,
                              void* d_out, int out_size) {
    const float* fm    = (const float*)d_in[0];
    const float* depth = (const float*)d_in[1];
    const float* wa    = (const float*)d_in[2];
    const float* ba    = (const float*)d_in[3];
    const float* wb    = (const float*)d_in[4];
    const float* bb    = (const float*)d_in[5];
    const float* wc    = (const float*)d_in[6];
    const float* bc    = (const float*)d_in[7];
    const float* wd    = (const float*)d_in[8];
    const float* bd    = (const float*)d_in[9];
    float* out = (float*)d_out;

    const int smem_bytes = SMEM_FLOATS * sizeof(float);
    cudaFuncSetAttribute(attn_kernel, cudaFuncAttributeMaxDynamicSharedMemorySize, smem_bytes);

    binkv_kernel<<<dim3(NB / BPB, BATCH), 512>>>(depth, wa, ba, wc, bc, wd, bd);

    // attn with Programmatic Dependent Launch: starts during binkv, self-syncs
    cudaLaunchAttribute attrs[1];
    attrs[0].id = cudaLaunchAttributeProgrammaticStreamSerialization;
    attrs[0].val.programmaticStreamSerializationAllowed = 1;
    cudaLaunchConfig_t cfg = {};
    cfg.gridDim  = dim3(NPIX / 128, BATCH);
    cfg.blockDim = dim3(512, 1, 1);
    cfg.dynamicSmemBytes = smem_bytes;
    cfg.stream = 0;
    cfg.attrs = attrs;
    cfg.numAttrs = 1;
    cudaLaunchKernelEx(&cfg, attn_kernel, fm, wb, bb, out);
}